// round 1
// baseline (speedup 1.0000x reference)
#include <cuda_runtime.h>
#include <math.h>

#define N_NODES 50000
#define N_EDGES 800000
#define HID     128
#define NHEAD   4
#define DH      32
#define OUTD    64

// ---------------- scratch (device globals; no allocations allowed) ----------
__device__ float g_q [N_NODES * HID];
__device__ float g_k [N_NODES * HID];
__device__ float g_v [N_NODES * HID];
__device__ float g_sk[N_NODES * HID];
__device__ float g_h [N_NODES * HID];
__device__ float g_t1[N_NODES * HID];
__device__ float g_t2[N_NODES * HID];
__device__ int   g_deg [N_NODES];
__device__ int   g_off [N_NODES + 1];
__device__ int   g_cur [N_NODES];
__device__ int   g_ssrc[N_EDGES];
__device__ float g_sattr[N_EDGES * 3];

// ---------------- edge sorting: histogram + scan + scatter ------------------
__global__ void zero_deg_kernel() {
    int i = blockIdx.x * blockDim.x + threadIdx.x;
    if (i < N_NODES) g_deg[i] = 0;
}

__global__ void hist_kernel(const int* __restrict__ ei) {
    int e = blockIdx.x * blockDim.x + threadIdx.x;
    if (e < N_EDGES) atomicAdd(&g_deg[ei[N_EDGES + e]], 1);
}

// single-block exclusive scan over g_deg -> g_off, g_cur
__global__ void scan_kernel() {
    __shared__ int wsum[32];
    __shared__ int carry_s;
    int tid = threadIdx.x, lane = tid & 31, wid = tid >> 5;
    if (tid == 0) carry_s = 0;
    __syncthreads();
    for (int base = 0; base < N_NODES; base += 1024) {
        int i = base + tid;
        int v = (i < N_NODES) ? g_deg[i] : 0;
        int x = v;
        #pragma unroll
        for (int d = 1; d < 32; d <<= 1) {
            int y = __shfl_up_sync(0xffffffffu, x, d);
            if (lane >= d) x += y;
        }
        if (lane == 31) wsum[wid] = x;
        __syncthreads();
        if (wid == 0) {
            int s = wsum[lane];
            #pragma unroll
            for (int d = 1; d < 32; d <<= 1) {
                int y = __shfl_up_sync(0xffffffffu, s, d);
                if (lane >= d) s += y;
            }
            wsum[lane] = s;
        }
        __syncthreads();
        int incl = x + (wid > 0 ? wsum[wid - 1] : 0) + carry_s;
        if (i < N_NODES) { g_off[i] = incl - v; g_cur[i] = incl - v; }
        __syncthreads();
        if (tid == 1023) carry_s = incl;
        __syncthreads();
    }
    if (tid == 0) g_off[N_NODES] = carry_s;
}

__global__ void scatter_kernel(const int* __restrict__ ei, const float* __restrict__ attr) {
    int e = blockIdx.x * blockDim.x + threadIdx.x;
    if (e < N_EDGES) {
        int dst = ei[N_EDGES + e];
        int pos = atomicAdd(&g_cur[dst], 1);
        g_ssrc[pos] = ei[e];
        g_sattr[3 * pos + 0] = attr[3 * e + 0];
        g_sattr[3 * pos + 1] = attr[3 * e + 1];
        g_sattr[3 * pos + 2] = attr[3 * e + 2];
    }
}

// ---------------- GEMM: C[M,Nout] = A[M,128] * B[Nout,128]^T (+bias,gelu,res)
__device__ __forceinline__ float gelu_f(float x) {
    float x3 = x * x * x;
    float u = 0.7978845608028654f * (x + 0.044715f * x3);
    return 0.5f * x * (1.0f + tanhf(u));
}

#define BM 128
#define BN 64
#define BK 16

__global__ __launch_bounds__(256) void gemm_kernel(
    const float* __restrict__ A, const float* __restrict__ B,
    const float* __restrict__ bias, const float* __restrict__ res,
    float* __restrict__ C, int M, int Nout, int act)
{
    __shared__ float As[BK][BM + 4];
    __shared__ float Bs[BK][BN + 4];
    int t  = threadIdx.x;
    int m0 = blockIdx.x * BM;
    int n0 = blockIdx.y * BN;
    int tr = t >> 4;      // 0..15 -> rows tr*8..+7
    int tc = t & 15;      // 0..15 -> cols tc*4..+3
    int lrow = t >> 2;    // 0..63
    int lk   = (t & 3) * 4;

    float acc[8][4];
    #pragma unroll
    for (int i = 0; i < 8; i++)
        #pragma unroll
        for (int j = 0; j < 4; j++) acc[i][j] = 0.f;

    for (int k0 = 0; k0 < 128; k0 += BK) {
        #pragma unroll
        for (int l = 0; l < 2; l++) {
            int r  = lrow + l * 64;
            int gr = m0 + r;
            float4 av = (gr < M) ? *(const float4*)(A + (size_t)gr * 128 + k0 + lk)
                                 : make_float4(0.f, 0.f, 0.f, 0.f);
            As[lk + 0][r] = av.x; As[lk + 1][r] = av.y;
            As[lk + 2][r] = av.z; As[lk + 3][r] = av.w;
        }
        {
            float4 bv = *(const float4*)(B + (size_t)(n0 + lrow) * 128 + k0 + lk);
            Bs[lk + 0][lrow] = bv.x; Bs[lk + 1][lrow] = bv.y;
            Bs[lk + 2][lrow] = bv.z; Bs[lk + 3][lrow] = bv.w;
        }
        __syncthreads();
        #pragma unroll
        for (int k = 0; k < BK; k++) {
            float a[8], b[4];
            #pragma unroll
            for (int i = 0; i < 8; i++) a[i] = As[k][tr * 8 + i];
            #pragma unroll
            for (int j = 0; j < 4; j++) b[j] = Bs[k][tc * 4 + j];
            #pragma unroll
            for (int i = 0; i < 8; i++)
                #pragma unroll
                for (int j = 0; j < 4; j++) acc[i][j] = fmaf(a[i], b[j], acc[i][j]);
        }
        __syncthreads();
    }

    #pragma unroll
    for (int i = 0; i < 8; i++) {
        int row = m0 + tr * 8 + i;
        if (row >= M) continue;
        #pragma unroll
        for (int j = 0; j < 4; j++) {
            int col = n0 + tc * 4 + j;
            float v = acc[i][j];
            if (bias) v += bias[col];
            if (act)  v = gelu_f(v);
            if (res)  v += res[(size_t)row * Nout + col];
            C[(size_t)row * Nout + col] = v;
        }
    }
}

// ---------------- edge attention: one warp per destination node --------------
// out[n] = (sum_e softmax(alpha)_e * (v[src]+e)) + skip[n], online softmax
__global__ __launch_bounds__(128) void attn_kernel(
    const float* __restrict__ q, const float* __restrict__ k,
    const float* __restrict__ v, const float* __restrict__ skip,
    const float* __restrict__ We, float* __restrict__ out)
{
    __shared__ float we_s[HID * 3];
    int tid = threadIdx.x;
    for (int i = tid; i < HID * 3; i += blockDim.x) we_s[i] = We[i];
    __syncthreads();

    int warp = blockIdx.x * (blockDim.x >> 5) + (tid >> 5);
    if (warp >= N_NODES) return;
    int lane = tid & 31;
    int col  = (lane >> 3) * DH + (lane & 7) * 4;  // head*32 + sub*4

    float4 qv = *(const float4*)(q + (size_t)warp * HID + col);
    float m = -INFINITY, ssum = 0.f;
    float ox = 0.f, oy = 0.f, oz = 0.f, ow = 0.f;

    int e0 = g_off[warp], e1 = g_off[warp + 1];
    for (int e = e0; e < e1; e++) {
        int src = g_ssrc[e];
        float a0 = g_sattr[3 * e + 0];
        float a1 = g_sattr[3 * e + 1];
        float a2 = g_sattr[3 * e + 2];
        float4 kv = *(const float4*)(k + (size_t)src * HID + col);
        float4 vv = *(const float4*)(v + (size_t)src * HID + col);
        float ec0 = fmaf(a0, we_s[3*(col+0)+0], fmaf(a1, we_s[3*(col+0)+1], a2 * we_s[3*(col+0)+2]));
        float ec1 = fmaf(a0, we_s[3*(col+1)+0], fmaf(a1, we_s[3*(col+1)+1], a2 * we_s[3*(col+1)+2]));
        float ec2 = fmaf(a0, we_s[3*(col+2)+0], fmaf(a1, we_s[3*(col+2)+1], a2 * we_s[3*(col+2)+2]));
        float ec3 = fmaf(a0, we_s[3*(col+3)+0], fmaf(a1, we_s[3*(col+3)+1], a2 * we_s[3*(col+3)+2]));
        float kx = kv.x + ec0, ky = kv.y + ec1, kz = kv.z + ec2, kw = kv.w + ec3;
        float dot = qv.x * kx + qv.y * ky + qv.z * kz + qv.w * kw;
        dot += __shfl_xor_sync(0xffffffffu, dot, 1);
        dot += __shfl_xor_sync(0xffffffffu, dot, 2);
        dot += __shfl_xor_sync(0xffffffffu, dot, 4);
        float alpha = dot * 0.17677669529663687f;   // 1/sqrt(32)
        float nm = fmaxf(m, alpha);
        float sc = __expf(m - nm);
        float p  = __expf(alpha - nm);
        ssum = ssum * sc + p;
        ox = ox * sc + p * (vv.x + ec0);
        oy = oy * sc + p * (vv.y + ec1);
        oz = oz * sc + p * (vv.z + ec2);
        ow = ow * sc + p * (vv.w + ec3);
        m = nm;
    }
    float inv = 1.0f / fmaxf(ssum, 1e-16f);
    float4 sk = *(const float4*)(skip + (size_t)warp * HID + col);
    float4 o4 = make_float4(ox * inv + sk.x, oy * inv + sk.y,
                            oz * inv + sk.z, ow * inv + sk.w);
    *(float4*)(out + (size_t)warp * HID + col) = o4;
}

// ---------------- launch ----------------------------------------------------
static inline void run_gemm(cudaStream_t s, const float* A, const float* B,
                            const float* bias, const float* res, float* C,
                            int M, int Nout, int act) {
    dim3 grid((M + BM - 1) / BM, Nout / BN);
    gemm_kernel<<<grid, 256, 0, s>>>(A, B, bias, res, C, M, Nout, act);
}

extern "C" void kernel_launch(void* const* d_in, const int* in_sizes, int n_in,
                              void* d_out, int out_size) {
    const float* x    = (const float*)d_in[0];
    const int*   ei   = (const int*)  d_in[1];
    const float* attr = (const float*)d_in[2];
    const float* Wq1 = (const float*)d_in[3],  *Wk1 = (const float*)d_in[4];
    const float* Wv1 = (const float*)d_in[5],  *We1 = (const float*)d_in[6];
    const float* Ws1 = (const float*)d_in[7];
    const float* M1a = (const float*)d_in[8],  *b1a = (const float*)d_in[9];
    const float* M1b = (const float*)d_in[10], *b1b = (const float*)d_in[11];
    const float* Wq2 = (const float*)d_in[12], *Wk2 = (const float*)d_in[13];
    const float* Wv2 = (const float*)d_in[14], *We2 = (const float*)d_in[15];
    const float* Ws2 = (const float*)d_in[16];
    const float* M2a = (const float*)d_in[17], *b2a = (const float*)d_in[18];
    const float* M2b = (const float*)d_in[19], *b2b = (const float*)d_in[20];
    const float* Wf1 = (const float*)d_in[21], *bf1 = (const float*)d_in[22];
    const float* Wf2 = (const float*)d_in[23], *bf2 = (const float*)d_in[24];
    float* out = (float*)d_out;

    float *q, *k, *v, *sk, *h, *t1, *t2;
    cudaGetSymbolAddress((void**)&q,  g_q);
    cudaGetSymbolAddress((void**)&k,  g_k);
    cudaGetSymbolAddress((void**)&v,  g_v);
    cudaGetSymbolAddress((void**)&sk, g_sk);
    cudaGetSymbolAddress((void**)&h,  g_h);
    cudaGetSymbolAddress((void**)&t1, g_t1);
    cudaGetSymbolAddress((void**)&t2, g_t2);

    cudaStream_t s = 0;  // harness captures the default-ish stream it passes work on

    // edge sort (per call; deterministic work)
    zero_deg_kernel<<<(N_NODES + 255) / 256, 256, 0, s>>>();
    hist_kernel<<<(N_EDGES + 255) / 256, 256, 0, s>>>(ei);
    scan_kernel<<<1, 1024, 0, s>>>();
    scatter_kernel<<<(N_EDGES + 255) / 256, 256, 0, s>>>(ei, attr);

    int ablocks = (N_NODES * 32 + 127) / 128;

    // ---- layer 1 conv ----
    run_gemm(s, x, Wq1, nullptr, nullptr, q,  N_NODES, HID, 0);
    run_gemm(s, x, Wk1, nullptr, nullptr, k,  N_NODES, HID, 0);
    run_gemm(s, x, Wv1, nullptr, nullptr, v,  N_NODES, HID, 0);
    run_gemm(s, x, Ws1, nullptr, nullptr, sk, N_NODES, HID, 0);
    attn_kernel<<<ablocks, 128, 0, s>>>(q, k, v, sk, We1, h);
    // ---- layer 1 MLP with residual ----
    run_gemm(s, h,  M1a, b1a, nullptr, t1, N_NODES, HID, 1);
    run_gemm(s, t1, M1b, b1b, h,       t2, N_NODES, HID, 1);

    // ---- layer 2 conv ----
    run_gemm(s, t2, Wq2, nullptr, nullptr, q,  N_NODES, HID, 0);
    run_gemm(s, t2, Wk2, nullptr, nullptr, k,  N_NODES, HID, 0);
    run_gemm(s, t2, Wv2, nullptr, nullptr, v,  N_NODES, HID, 0);
    run_gemm(s, t2, Ws2, nullptr, nullptr, sk, N_NODES, HID, 0);
    attn_kernel<<<ablocks, 128, 0, s>>>(q, k, v, sk, We2, h);
    // ---- layer 2 MLP with residual ----
    run_gemm(s, h,  M2a, b2a, nullptr, t1, N_NODES, HID, 1);
    run_gemm(s, t1, M2b, b2b, h,       t2, N_NODES, HID, 1);

    // ---- final MLP (plain_last=False: gelu on both) ----
    run_gemm(s, t2, Wf1, bf1, nullptr, t1, N_NODES, HID, 1);
    run_gemm(s, t1, Wf2, bf2, nullptr, out, N_NODES, OUTD, 1);
}

// round 4
// speedup vs baseline: 1.1897x; 1.1897x over previous
#include <cuda_runtime.h>
#include <cuda_bf16.h>
#include <math.h>
#include <stdint.h>

#define N_NODES 50000
#define N_EDGES 800000
#define HID     128
#define NHEAD   4
#define DH      32
#define OUTD    64

// ======================= scratch (device globals) ===========================
__device__ float g_q [N_NODES * HID];
__device__ float g_k [N_NODES * HID];
__device__ float g_v [N_NODES * HID];
__device__ float g_sk[N_NODES * HID];
__device__ float g_h [N_NODES * HID];
__device__ float g_t1[N_NODES * HID];
__device__ float g_t2[N_NODES * HID];
__device__ int   g_deg [N_NODES];
__device__ int   g_off [N_NODES + 1];
__device__ int   g_cur [N_NODES];
__device__ int   g_ssrc[N_EDGES];
__device__ float g_sattr[N_EDGES * 3];

// bf16 hi/lo mirrors of activations feeding tensor-core GEMMs
__device__ __nv_bfloat16 g_xhi [N_NODES * HID];
__device__ __nv_bfloat16 g_xlo [N_NODES * HID];
__device__ __nv_bfloat16 g_hhi [N_NODES * HID];
__device__ __nv_bfloat16 g_hlo [N_NODES * HID];
__device__ __nv_bfloat16 g_t1hi[N_NODES * HID];
__device__ __nv_bfloat16 g_t1lo[N_NODES * HID];
__device__ __nv_bfloat16 g_t2hi[N_NODES * HID];
__device__ __nv_bfloat16 g_t2lo[N_NODES * HID];
__device__ __nv_bfloat16 g_whi[14 * 16384];
__device__ __nv_bfloat16 g_wlo[14 * 16384];

// ======================= edge sorting =======================================
__global__ void zero_deg_kernel() {
    int i = blockIdx.x * blockDim.x + threadIdx.x;
    if (i < N_NODES) g_deg[i] = 0;
}

__global__ void hist_kernel(const int* __restrict__ ei) {
    int e = blockIdx.x * blockDim.x + threadIdx.x;
    if (e < N_EDGES) atomicAdd(&g_deg[ei[N_EDGES + e]], 1);
}

__global__ void scan_kernel() {
    __shared__ int wsum[32];
    __shared__ int carry_s;
    int tid = threadIdx.x, lane = tid & 31, wid = tid >> 5;
    if (tid == 0) carry_s = 0;
    __syncthreads();
    for (int base = 0; base < N_NODES; base += 1024) {
        int i = base + tid;
        int v = (i < N_NODES) ? g_deg[i] : 0;
        int x = v;
        #pragma unroll
        for (int d = 1; d < 32; d <<= 1) {
            int y = __shfl_up_sync(0xffffffffu, x, d);
            if (lane >= d) x += y;
        }
        if (lane == 31) wsum[wid] = x;
        __syncthreads();
        if (wid == 0) {
            int s = wsum[lane];
            #pragma unroll
            for (int d = 1; d < 32; d <<= 1) {
                int y = __shfl_up_sync(0xffffffffu, s, d);
                if (lane >= d) s += y;
            }
            wsum[lane] = s;
        }
        __syncthreads();
        int incl = x + (wid > 0 ? wsum[wid - 1] : 0) + carry_s;
        if (i < N_NODES) { g_off[i] = incl - v; g_cur[i] = incl - v; }
        __syncthreads();
        if (tid == 1023) carry_s = incl;
        __syncthreads();
    }
    if (tid == 0) g_off[N_NODES] = carry_s;
}

__global__ void scatter_kernel(const int* __restrict__ ei, const float* __restrict__ attr) {
    int e = blockIdx.x * blockDim.x + threadIdx.x;
    if (e < N_EDGES) {
        int dst = ei[N_EDGES + e];
        int pos = atomicAdd(&g_cur[dst], 1);
        g_ssrc[pos] = ei[e];
        g_sattr[3 * pos + 0] = attr[3 * e + 0];
        g_sattr[3 * pos + 1] = attr[3 * e + 1];
        g_sattr[3 * pos + 2] = attr[3 * e + 2];
    }
}

// ======================= fp32 -> bf16 hi/lo split ===========================
__global__ void split_kernel(const float* __restrict__ s,
                             __nv_bfloat16* __restrict__ hi,
                             __nv_bfloat16* __restrict__ lo, int n) {
    int i = blockIdx.x * blockDim.x + threadIdx.x;
    if (i < n) {
        float v = s[i];
        __nv_bfloat16 h = __float2bfloat16(v);
        hi[i] = h;
        lo[i] = __float2bfloat16(v - __bfloat162float(h));
    }
}

// ======================= GELU ==============================================
__device__ __forceinline__ float gelu_f(float x) {
    float x3 = x * x * x;
    float u = 0.7978845608028654f * (x + 0.044715f * x3);
    return 0.5f * x * (1.0f + tanhf(u));
}

// ======================= HMMA mma.sync GEMM =================================
// C[M,Nout] = (Ahi+Alo)[M,128] @ (Bhi+Blo)[Nout,128]^T via
// mma.sync.m16n8k16 bf16, fp32 acc, 3 passes (AhBh + AhBl + AlBh).
// smem row stride 136 bf16 = 68 words (68 mod 32 = 4) -> conflict-free frags.

#define SROW 136
#define OFF_AH 0
#define OFF_AL 34816
#define OFF_BH 69632
#define OFF_BL 104448
#define MMA_SMEM 139264

__device__ __forceinline__ uint32_t lds32(const __nv_bfloat16* p) {
    return *(const uint32_t*)p;
}

__device__ __forceinline__ void mma16816(float* c,
    uint32_t a0, uint32_t a1, uint32_t a2, uint32_t a3,
    uint32_t b0, uint32_t b1) {
    asm volatile(
        "mma.sync.aligned.m16n8k16.row.col.f32.bf16.bf16.f32 "
        "{%0,%1,%2,%3}, {%4,%5,%6,%7}, {%8,%9}, {%0,%1,%2,%3};"
        : "+f"(c[0]), "+f"(c[1]), "+f"(c[2]), "+f"(c[3])
        : "r"(a0), "r"(a1), "r"(a2), "r"(a3), "r"(b0), "r"(b1));
}

__global__ __launch_bounds__(512, 1) void mma_gemm(
    const __nv_bfloat16* __restrict__ Ahi, const __nv_bfloat16* __restrict__ Alo,
    const __nv_bfloat16* __restrict__ Bhi, const __nv_bfloat16* __restrict__ Blo,
    const float* __restrict__ bias, const float* __restrict__ res,
    float* __restrict__ C, __nv_bfloat16* __restrict__ Chi, __nv_bfloat16* __restrict__ Clo,
    int M, int Nout, int act)
{
    extern __shared__ char smem[];
    __nv_bfloat16* sAh = (__nv_bfloat16*)(smem + OFF_AH);
    __nv_bfloat16* sAl = (__nv_bfloat16*)(smem + OFF_AL);
    __nv_bfloat16* sBh = (__nv_bfloat16*)(smem + OFF_BH);
    __nv_bfloat16* sBl = (__nv_bfloat16*)(smem + OFF_BL);
    int tid = threadIdx.x;
    int m0 = blockIdx.x * 128;

    // ---- stage A (128 rows x 16 uint4; 512 threads x 4 uint4 each) ----
    {
        int row = tid >> 2;          // 4 threads per row
        int u0  = (tid & 3) * 4;     // each thread: 4 x uint4 (32 bf16)
        int gr  = m0 + row;
        bool ok = gr < M;
        const uint4* ah = (const uint4*)(Ahi + (size_t)gr * 128);
        const uint4* al = (const uint4*)(Alo + (size_t)gr * 128);
        uint4 z = make_uint4(0u, 0u, 0u, 0u);
        #pragma unroll
        for (int u = u0; u < u0 + 4; u++) {
            *(uint4*)(&sAh[row * SROW + u * 8]) = ok ? ah[u] : z;
            *(uint4*)(&sAl[row * SROW + u * 8]) = ok ? al[u] : z;
        }
    }
    // ---- stage B (Nout rows x 16 uint4; 4 threads x 4 uint4 per row) ----
    if (tid < Nout * 4) {
        int row = tid >> 2;
        int u0  = (tid & 3) * 4;
        const uint4* bh = (const uint4*)(Bhi + (size_t)row * 128);
        const uint4* bl = (const uint4*)(Blo + (size_t)row * 128);
        #pragma unroll
        for (int u = u0; u < u0 + 4; u++) {
            *(uint4*)(&sBh[row * SROW + u * 8]) = bh[u];
            *(uint4*)(&sBl[row * SROW + u * 8]) = bl[u];
        }
    }
    __syncthreads();

    int lane = tid & 31, wid = tid >> 5;
    int grp = lane >> 2, qd = lane & 3;
    int mt = (wid >> 1) * 16;                 // warp row block
    int NT = Nout >> 3;                       // n-tiles of 8
    int ntBeg = (wid & 1) * (NT >> 1);
    int ntN   = NT >> 1;                      // tiles this warp owns (<=8)

    float acc[8][4];
    #pragma unroll
    for (int i = 0; i < 8; i++)
        #pragma unroll
        for (int j = 0; j < 4; j++) acc[i][j] = 0.f;

    for (int kt = 0; kt < 128; kt += 16) {
        int aoff = (mt + grp) * SROW + kt + 2 * qd;
        uint32_t ah0 = lds32(sAh + aoff);
        uint32_t ah1 = lds32(sAh + aoff + 8 * SROW);
        uint32_t ah2 = lds32(sAh + aoff + 8);
        uint32_t ah3 = lds32(sAh + aoff + 8 * SROW + 8);
        uint32_t al0 = lds32(sAl + aoff);
        uint32_t al1 = lds32(sAl + aoff + 8 * SROW);
        uint32_t al2 = lds32(sAl + aoff + 8);
        uint32_t al3 = lds32(sAl + aoff + 8 * SROW + 8);
        #pragma unroll
        for (int t = 0; t < 8; t++) {
            if (t >= ntN) break;
            int nt = ntBeg + t;
            int boff = (nt * 8 + grp) * SROW + kt + 2 * qd;
            uint32_t bh0 = lds32(sBh + boff);
            uint32_t bh1 = lds32(sBh + boff + 8);
            uint32_t bl0 = lds32(sBl + boff);
            uint32_t bl1 = lds32(sBl + boff + 8);
            mma16816(acc[t], ah0, ah1, ah2, ah3, bh0, bh1);
            mma16816(acc[t], ah0, ah1, ah2, ah3, bl0, bl1);
            mma16816(acc[t], al0, al1, al2, al3, bh0, bh1);
        }
    }

    // ---- epilogue ----
    // c0,c1 -> (row = mt+grp,   col, col+1); c2,c3 -> (row+8, col, col+1)
    #pragma unroll
    for (int t = 0; t < 8; t++) {
        if (t >= ntN) break;
        int nt = ntBeg + t;
        int col = nt * 8 + 2 * qd;
        float bsum0 = bias ? bias[col]     : 0.f;
        float bsum1 = bias ? bias[col + 1] : 0.f;
        #pragma unroll
        for (int half = 0; half < 2; half++) {
            int row = m0 + mt + grp + half * 8;
            if (row >= M) continue;
            float v0 = acc[t][half * 2 + 0] + bsum0;
            float v1 = acc[t][half * 2 + 1] + bsum1;
            if (act) { v0 = gelu_f(v0); v1 = gelu_f(v1); }
            size_t base = (size_t)row * Nout + col;
            if (res) { v0 += res[base]; v1 += res[base + 1]; }
            *(float2*)(C + base) = make_float2(v0, v1);
            if (Chi) {
                __nv_bfloat16 h0 = __float2bfloat16(v0);
                __nv_bfloat16 h1 = __float2bfloat16(v1);
                __nv_bfloat162 hh; hh.x = h0; hh.y = h1;
                __nv_bfloat162 ll;
                ll.x = __float2bfloat16(v0 - __bfloat162float(h0));
                ll.y = __float2bfloat16(v1 - __bfloat162float(h1));
                *(__nv_bfloat162*)(Chi + base) = hh;
                *(__nv_bfloat162*)(Clo + base) = ll;
            }
        }
    }
}

// ======================= edge attention =====================================
__global__ __launch_bounds__(128) void attn_kernel(
    const float* __restrict__ q, const float* __restrict__ k,
    const float* __restrict__ v, const float* __restrict__ skip,
    const float* __restrict__ We, float* __restrict__ out,
    __nv_bfloat16* __restrict__ outhi, __nv_bfloat16* __restrict__ outlo)
{
    __shared__ float we_s[HID * 3];
    int tid = threadIdx.x;
    for (int i = tid; i < HID * 3; i += blockDim.x) we_s[i] = We[i];
    __syncthreads();

    int warp = blockIdx.x * (blockDim.x >> 5) + (tid >> 5);
    if (warp >= N_NODES) return;
    int lane = tid & 31;
    int col  = (lane >> 3) * DH + (lane & 7) * 4;

    float4 qv = *(const float4*)(q + (size_t)warp * HID + col);
    float m = -INFINITY, ssum = 0.f;
    float ox = 0.f, oy = 0.f, oz = 0.f, ow = 0.f;

    int e0 = g_off[warp], e1 = g_off[warp + 1];
    for (int e = e0; e < e1; e++) {
        int src = g_ssrc[e];
        float a0 = g_sattr[3 * e + 0];
        float a1 = g_sattr[3 * e + 1];
        float a2 = g_sattr[3 * e + 2];
        float4 kv = *(const float4*)(k + (size_t)src * HID + col);
        float4 vv = *(const float4*)(v + (size_t)src * HID + col);
        float ec0 = fmaf(a0, we_s[3*(col+0)+0], fmaf(a1, we_s[3*(col+0)+1], a2 * we_s[3*(col+0)+2]));
        float ec1 = fmaf(a0, we_s[3*(col+1)+0], fmaf(a1, we_s[3*(col+1)+1], a2 * we_s[3*(col+1)+2]));
        float ec2 = fmaf(a0, we_s[3*(col+2)+0], fmaf(a1, we_s[3*(col+2)+1], a2 * we_s[3*(col+2)+2]));
        float ec3 = fmaf(a0, we_s[3*(col+3)+0], fmaf(a1, we_s[3*(col+3)+1], a2 * we_s[3*(col+3)+2]));
        float kx = kv.x + ec0, ky = kv.y + ec1, kz = kv.z + ec2, kw = kv.w + ec3;
        float dot = qv.x * kx + qv.y * ky + qv.z * kz + qv.w * kw;
        dot += __shfl_xor_sync(0xffffffffu, dot, 1);
        dot += __shfl_xor_sync(0xffffffffu, dot, 2);
        dot += __shfl_xor_sync(0xffffffffu, dot, 4);
        float alpha = dot * 0.17677669529663687f;
        float nm = fmaxf(m, alpha);
        float sc = __expf(m - nm);
        float p  = __expf(alpha - nm);
        ssum = ssum * sc + p;
        ox = ox * sc + p * (vv.x + ec0);
        oy = oy * sc + p * (vv.y + ec1);
        oz = oz * sc + p * (vv.z + ec2);
        ow = ow * sc + p * (vv.w + ec3);
        m = nm;
    }
    float inv = 1.0f / fmaxf(ssum, 1e-16f);
    float4 sk = *(const float4*)(skip + (size_t)warp * HID + col);
    float o0 = ox * inv + sk.x, o1 = oy * inv + sk.y;
    float o2 = oz * inv + sk.z, o3 = ow * inv + sk.w;
    size_t base = (size_t)warp * HID + col;
    *(float4*)(out + base) = make_float4(o0, o1, o2, o3);

    float vs[4] = {o0, o1, o2, o3};
    #pragma unroll
    for (int pr = 0; pr < 2; pr++) {
        float v0 = vs[pr * 2], v1 = vs[pr * 2 + 1];
        __nv_bfloat16 h0 = __float2bfloat16(v0);
        __nv_bfloat16 h1 = __float2bfloat16(v1);
        __nv_bfloat162 hh; hh.x = h0; hh.y = h1;
        __nv_bfloat162 ll;
        ll.x = __float2bfloat16(v0 - __bfloat162float(h0));
        ll.y = __float2bfloat16(v1 - __bfloat162float(h1));
        *(__nv_bfloat162*)(outhi + base + pr * 2) = hh;
        *(__nv_bfloat162*)(outlo + base + pr * 2) = ll;
    }
}

// ======================= launch =============================================
static inline void run_mm(cudaStream_t s,
                          const __nv_bfloat16* Ahi, const __nv_bfloat16* Alo,
                          const __nv_bfloat16* Bhi, const __nv_bfloat16* Blo,
                          const float* bias, const float* res,
                          float* C, __nv_bfloat16* Chi, __nv_bfloat16* Clo,
                          int M, int Nout, int act) {
    int grid = (M + 127) / 128;
    mma_gemm<<<grid, 512, MMA_SMEM, s>>>(Ahi, Alo, Bhi, Blo, bias, res, C, Chi, Clo, M, Nout, act);
}

extern "C" void kernel_launch(void* const* d_in, const int* in_sizes, int n_in,
                              void* d_out, int out_size) {
    const float* x    = (const float*)d_in[0];
    const int*   ei   = (const int*)  d_in[1];
    const float* attr = (const float*)d_in[2];
    const float* Wq1 = (const float*)d_in[3],  *Wk1 = (const float*)d_in[4];
    const float* Wv1 = (const float*)d_in[5],  *We1 = (const float*)d_in[6];
    const float* Ws1 = (const float*)d_in[7];
    const float* M1a = (const float*)d_in[8],  *b1a = (const float*)d_in[9];
    const float* M1b = (const float*)d_in[10], *b1b = (const float*)d_in[11];
    const float* Wq2 = (const float*)d_in[12], *Wk2 = (const float*)d_in[13];
    const float* Wv2 = (const float*)d_in[14], *We2 = (const float*)d_in[15];
    const float* Ws2 = (const float*)d_in[16];
    const float* M2a = (const float*)d_in[17], *b2a = (const float*)d_in[18];
    const float* M2b = (const float*)d_in[19], *b2b = (const float*)d_in[20];
    const float* Wf1 = (const float*)d_in[21], *bf1 = (const float*)d_in[22];
    const float* Wf2 = (const float*)d_in[23], *bf2 = (const float*)d_in[24];
    float* out = (float*)d_out;

    float *q, *k, *v, *sk, *h, *t1, *t2;
    cudaGetSymbolAddress((void**)&q,  g_q);
    cudaGetSymbolAddress((void**)&k,  g_k);
    cudaGetSymbolAddress((void**)&v,  g_v);
    cudaGetSymbolAddress((void**)&sk, g_sk);
    cudaGetSymbolAddress((void**)&h,  g_h);
    cudaGetSymbolAddress((void**)&t1, g_t1);
    cudaGetSymbolAddress((void**)&t2, g_t2);

    __nv_bfloat16 *xhi, *xlo, *hhi, *hlo, *t1hi, *t1lo, *t2hi, *t2lo, *whi, *wlo;
    cudaGetSymbolAddress((void**)&xhi,  g_xhi);
    cudaGetSymbolAddress((void**)&xlo,  g_xlo);
    cudaGetSymbolAddress((void**)&hhi,  g_hhi);
    cudaGetSymbolAddress((void**)&hlo,  g_hlo);
    cudaGetSymbolAddress((void**)&t1hi, g_t1hi);
    cudaGetSymbolAddress((void**)&t1lo, g_t1lo);
    cudaGetSymbolAddress((void**)&t2hi, g_t2hi);
    cudaGetSymbolAddress((void**)&t2lo, g_t2lo);
    cudaGetSymbolAddress((void**)&whi,  g_whi);
    cudaGetSymbolAddress((void**)&wlo,  g_wlo);

    cudaFuncSetAttribute(mma_gemm, cudaFuncAttributeMaxDynamicSharedMemorySize, MMA_SMEM);

    cudaStream_t s = 0;

    // ---- split weights (14 matrices) ----
    const float* wsrc[14] = {Wq1, Wk1, Wv1, Ws1, M1a, M1b, Wq2, Wk2, Wv2, Ws2, M2a, M2b, Wf1, Wf2};
    const int    wn[14]   = {16384,16384,16384,16384,16384,16384,16384,16384,16384,16384,16384,16384,16384,8192};
    for (int i = 0; i < 14; i++) {
        split_kernel<<<(wn[i] + 255) / 256, 256, 0, s>>>(wsrc[i], whi + i * 16384, wlo + i * 16384, wn[i]);
    }
    split_kernel<<<(N_NODES * HID + 255) / 256, 256, 0, s>>>(x, xhi, xlo, N_NODES * HID);

    // ---- edge sort ----
    zero_deg_kernel<<<(N_NODES + 255) / 256, 256, 0, s>>>();
    hist_kernel<<<(N_EDGES + 255) / 256, 256, 0, s>>>(ei);
    scan_kernel<<<1, 1024, 0, s>>>();
    scatter_kernel<<<(N_EDGES + 255) / 256, 256, 0, s>>>(ei, attr);

    int ablocks = (N_NODES * 32 + 127) / 128;
    #define WHI(i) (whi + (i) * 16384)
    #define WLO(i) (wlo + (i) * 16384)

    // ---- layer 1 conv ----
    run_mm(s, xhi, xlo, WHI(0), WLO(0), nullptr, nullptr, q,  nullptr, nullptr, N_NODES, HID, 0);
    run_mm(s, xhi, xlo, WHI(1), WLO(1), nullptr, nullptr, k,  nullptr, nullptr, N_NODES, HID, 0);
    run_mm(s, xhi, xlo, WHI(2), WLO(2), nullptr, nullptr, v,  nullptr, nullptr, N_NODES, HID, 0);
    run_mm(s, xhi, xlo, WHI(3), WLO(3), nullptr, nullptr, sk, nullptr, nullptr, N_NODES, HID, 0);
    attn_kernel<<<ablocks, 128, 0, s>>>(q, k, v, sk, We1, h, hhi, hlo);
    // ---- layer 1 MLP with residual ----
    run_mm(s, hhi,  hlo,  WHI(4), WLO(4), b1a, nullptr, t1, t1hi, t1lo, N_NODES, HID, 1);
    run_mm(s, t1hi, t1lo, WHI(5), WLO(5), b1b, h,       t2, t2hi, t2lo, N_NODES, HID, 1);

    // ---- layer 2 conv ----
    run_mm(s, t2hi, t2lo, WHI(6), WLO(6), nullptr, nullptr, q,  nullptr, nullptr, N_NODES, HID, 0);
    run_mm(s, t2hi, t2lo, WHI(7), WLO(7), nullptr, nullptr, k,  nullptr, nullptr, N_NODES, HID, 0);
    run_mm(s, t2hi, t2lo, WHI(8), WLO(8), nullptr, nullptr, v,  nullptr, nullptr, N_NODES, HID, 0);
    run_mm(s, t2hi, t2lo, WHI(9), WLO(9), nullptr, nullptr, sk, nullptr, nullptr, N_NODES, HID, 0);
    attn_kernel<<<ablocks, 128, 0, s>>>(q, k, v, sk, We2, h, hhi, hlo);
    // ---- layer 2 MLP with residual ----
    run_mm(s, hhi,  hlo,  WHI(10), WLO(10), b2a, nullptr, t1, t1hi, t1lo, N_NODES, HID, 1);
    run_mm(s, t1hi, t1lo, WHI(11), WLO(11), b2b, h,       t2, t2hi, t2lo, N_NODES, HID, 1);

    // ---- final MLP ----
    run_mm(s, t2hi, t2lo, WHI(12), WLO(12), bf1, nullptr, t1, t1hi, t1lo, N_NODES, HID, 1);
    run_mm(s, t1hi, t1lo, WHI(13), WLO(13), bf2, nullptr, out, nullptr, nullptr, N_NODES, OUTD, 1);
}

// round 5
// speedup vs baseline: 1.2420x; 1.0440x over previous
#include <cuda_runtime.h>
#include <cuda_bf16.h>
#include <math.h>
#include <stdint.h>

#define N_NODES 50000
#define N_EDGES 800000
#define HID     128
#define NHEAD   4
#define DH      32
#define OUTD    64

// ======================= scratch (device globals) ===========================
__device__ float g_q [N_NODES * HID];
__device__ float g_k [N_NODES * HID];
__device__ float g_v [N_NODES * HID];
__device__ float g_sk[N_NODES * HID];
__device__ float g_h [N_NODES * HID];
__device__ float g_t1[N_NODES * HID];
__device__ float g_t2[N_NODES * HID];
__device__ int   g_deg [N_NODES];
__device__ int   g_off [N_NODES + 1];
__device__ int   g_cur [N_NODES];
__device__ int   g_ssrc[N_EDGES];
__device__ float g_sattr[N_EDGES * 3];

__device__ __nv_bfloat16 g_xhi [N_NODES * HID];
__device__ __nv_bfloat16 g_xlo [N_NODES * HID];
__device__ __nv_bfloat16 g_hhi [N_NODES * HID];
__device__ __nv_bfloat16 g_hlo [N_NODES * HID];
__device__ __nv_bfloat16 g_t1hi[N_NODES * HID];
__device__ __nv_bfloat16 g_t1lo[N_NODES * HID];
__device__ __nv_bfloat16 g_t2hi[N_NODES * HID];
__device__ __nv_bfloat16 g_t2lo[N_NODES * HID];
__device__ __nv_bfloat16 g_whi[14 * 16384];
__device__ __nv_bfloat16 g_wlo[14 * 16384];

// ======================= fused weight split + deg zero ======================
struct WPtrs { const float* p[14]; };

#define WSPLIT_BLOCKS 864           // 13*64 + 32
#define ZERO_BLOCKS   196           // ceil(50000/256)

__global__ void wsplit_zero_kernel(WPtrs wp) {
    int b = blockIdx.x;
    if (b < WSPLIT_BLOCKS) {
        int mi, cb;
        if (b < 832) { mi = b >> 6; cb = b & 63; }
        else         { mi = 13;     cb = b - 832; }
        int i = cb * 256 + threadIdx.x;
        int n = (mi == 13) ? 8192 : 16384;
        if (i < n) {
            float v = wp.p[mi][i];
            __nv_bfloat16 h = __float2bfloat16(v);
            g_whi[mi * 16384 + i] = h;
            g_wlo[mi * 16384 + i] = __float2bfloat16(v - __bfloat162float(h));
        }
    } else {
        int i = (b - WSPLIT_BLOCKS) * 256 + threadIdx.x;
        if (i < N_NODES) g_deg[i] = 0;
    }
}

// ======================= edge sorting =======================================
__global__ void hist_kernel(const int* __restrict__ ei) {
    int e = blockIdx.x * blockDim.x + threadIdx.x;
    if (e < N_EDGES) atomicAdd(&g_deg[ei[N_EDGES + e]], 1);
}

__global__ void scan_kernel() {
    __shared__ int wsum[32];
    __shared__ int carry_s;
    int tid = threadIdx.x, lane = tid & 31, wid = tid >> 5;
    if (tid == 0) carry_s = 0;
    __syncthreads();
    for (int base = 0; base < N_NODES; base += 1024) {
        int i = base + tid;
        int v = (i < N_NODES) ? g_deg[i] : 0;
        int x = v;
        #pragma unroll
        for (int d = 1; d < 32; d <<= 1) {
            int y = __shfl_up_sync(0xffffffffu, x, d);
            if (lane >= d) x += y;
        }
        if (lane == 31) wsum[wid] = x;
        __syncthreads();
        if (wid == 0) {
            int s = wsum[lane];
            #pragma unroll
            for (int d = 1; d < 32; d <<= 1) {
                int y = __shfl_up_sync(0xffffffffu, s, d);
                if (lane >= d) s += y;
            }
            wsum[lane] = s;
        }
        __syncthreads();
        int incl = x + (wid > 0 ? wsum[wid - 1] : 0) + carry_s;
        if (i < N_NODES) { g_off[i] = incl - v; g_cur[i] = incl - v; }
        __syncthreads();
        if (tid == 1023) carry_s = incl;
        __syncthreads();
    }
    if (tid == 0) g_off[N_NODES] = carry_s;
}

__global__ void scatter_kernel(const int* __restrict__ ei, const float* __restrict__ attr) {
    int e = blockIdx.x * blockDim.x + threadIdx.x;
    if (e < N_EDGES) {
        int dst = ei[N_EDGES + e];
        int pos = atomicAdd(&g_cur[dst], 1);
        g_ssrc[pos] = ei[e];
        g_sattr[3 * pos + 0] = attr[3 * e + 0];
        g_sattr[3 * pos + 1] = attr[3 * e + 1];
        g_sattr[3 * pos + 2] = attr[3 * e + 2];
    }
}

// ======================= fp32 -> bf16 hi/lo split ===========================
__global__ void split_kernel(const float* __restrict__ s,
                             __nv_bfloat16* __restrict__ hi,
                             __nv_bfloat16* __restrict__ lo, int n) {
    int i = blockIdx.x * blockDim.x + threadIdx.x;
    if (i < n) {
        float v = s[i];
        __nv_bfloat16 h = __float2bfloat16(v);
        hi[i] = h;
        lo[i] = __float2bfloat16(v - __bfloat162float(h));
    }
}

// ======================= GELU ==============================================
__device__ __forceinline__ float gelu_f(float x) {
    float x3 = x * x * x;
    float u = 0.7978845608028654f * (x + 0.044715f * x3);
    return 0.5f * x * (1.0f + tanhf(u));
}

// ======================= HMMA mma.sync GEMM =================================
#define SROW 136
#define OFF_AH 0
#define OFF_AL 34816
#define OFF_BH 69632
#define OFF_BL 104448
#define MMA_SMEM 139264

__device__ __forceinline__ uint32_t lds32(const __nv_bfloat16* p) {
    return *(const uint32_t*)p;
}

__device__ __forceinline__ void mma16816(float* c,
    uint32_t a0, uint32_t a1, uint32_t a2, uint32_t a3,
    uint32_t b0, uint32_t b1) {
    asm volatile(
        "mma.sync.aligned.m16n8k16.row.col.f32.bf16.bf16.f32 "
        "{%0,%1,%2,%3}, {%4,%5,%6,%7}, {%8,%9}, {%0,%1,%2,%3};"
        : "+f"(c[0]), "+f"(c[1]), "+f"(c[2]), "+f"(c[3])
        : "r"(a0), "r"(a1), "r"(a2), "r"(a3), "r"(b0), "r"(b1));
}

// ---- shared device body: stage A/B, run 3-pass mainloop ----
__device__ __forceinline__ void gemm_stage_A(
    const __nv_bfloat16* Ahi, const __nv_bfloat16* Alo,
    __nv_bfloat16* sAh, __nv_bfloat16* sAl, int m0, int M, int tid)
{
    int row = tid >> 2;
    int u0  = (tid & 3) * 4;
    int gr  = m0 + row;
    bool ok = gr < M;
    const uint4* ah = (const uint4*)(Ahi + (size_t)gr * 128);
    const uint4* al = (const uint4*)(Alo + (size_t)gr * 128);
    uint4 z = make_uint4(0u, 0u, 0u, 0u);
    #pragma unroll
    for (int u = u0; u < u0 + 4; u++) {
        *(uint4*)(&sAh[row * SROW + u * 8]) = ok ? ah[u] : z;
        *(uint4*)(&sAl[row * SROW + u * 8]) = ok ? al[u] : z;
    }
}

__device__ __forceinline__ void gemm_stage_B(
    const __nv_bfloat16* Bhi, const __nv_bfloat16* Blo,
    __nv_bfloat16* sBh, __nv_bfloat16* sBl, int Nout, int tid)
{
    if (tid < Nout * 4) {
        int row = tid >> 2;
        int u0  = (tid & 3) * 4;
        const uint4* bh = (const uint4*)(Bhi + (size_t)row * 128);
        const uint4* bl = (const uint4*)(Blo + (size_t)row * 128);
        #pragma unroll
        for (int u = u0; u < u0 + 4; u++) {
            *(uint4*)(&sBh[row * SROW + u * 8]) = bh[u];
            *(uint4*)(&sBl[row * SROW + u * 8]) = bl[u];
        }
    }
}

__device__ __forceinline__ void gemm_mainloop(
    const __nv_bfloat16* sAh, const __nv_bfloat16* sAl,
    const __nv_bfloat16* sBh, const __nv_bfloat16* sBl,
    float acc[8][4], int mt, int grp, int qd, int ntBeg, int ntN)
{
    for (int kt = 0; kt < 128; kt += 16) {
        int aoff = (mt + grp) * SROW + kt + 2 * qd;
        uint32_t ah0 = lds32(sAh + aoff);
        uint32_t ah1 = lds32(sAh + aoff + 8 * SROW);
        uint32_t ah2 = lds32(sAh + aoff + 8);
        uint32_t ah3 = lds32(sAh + aoff + 8 * SROW + 8);
        uint32_t al0 = lds32(sAl + aoff);
        uint32_t al1 = lds32(sAl + aoff + 8 * SROW);
        uint32_t al2 = lds32(sAl + aoff + 8);
        uint32_t al3 = lds32(sAl + aoff + 8 * SROW + 8);
        #pragma unroll
        for (int t = 0; t < 8; t++) {
            if (t >= ntN) break;
            int nt = ntBeg + t;
            int boff = (nt * 8 + grp) * SROW + kt + 2 * qd;
            uint32_t bh0 = lds32(sBh + boff);
            uint32_t bh1 = lds32(sBh + boff + 8);
            uint32_t bl0 = lds32(sBl + boff);
            uint32_t bl1 = lds32(sBl + boff + 8);
            mma16816(acc[t], ah0, ah1, ah2, ah3, bh0, bh1);
            mma16816(acc[t], ah0, ah1, ah2, ah3, bl0, bl1);
            mma16816(acc[t], al0, al1, al2, al3, bh0, bh1);
        }
    }
}

// ---- general GEMM with epilogue options (MLP / final layers) ----
__global__ __launch_bounds__(512, 1) void mma_gemm(
    const __nv_bfloat16* __restrict__ Ahi, const __nv_bfloat16* __restrict__ Alo,
    const __nv_bfloat16* __restrict__ Bhi, const __nv_bfloat16* __restrict__ Blo,
    const float* __restrict__ bias, const float* __restrict__ res,
    float* __restrict__ C, __nv_bfloat16* __restrict__ Chi, __nv_bfloat16* __restrict__ Clo,
    int M, int Nout, int act)
{
    extern __shared__ char smem[];
    __nv_bfloat16* sAh = (__nv_bfloat16*)(smem + OFF_AH);
    __nv_bfloat16* sAl = (__nv_bfloat16*)(smem + OFF_AL);
    __nv_bfloat16* sBh = (__nv_bfloat16*)(smem + OFF_BH);
    __nv_bfloat16* sBl = (__nv_bfloat16*)(smem + OFF_BL);
    int tid = threadIdx.x;
    int m0 = blockIdx.x * 128;

    gemm_stage_A(Ahi, Alo, sAh, sAl, m0, M, tid);
    gemm_stage_B(Bhi, Blo, sBh, sBl, Nout, tid);
    __syncthreads();

    int lane = tid & 31, wid = tid >> 5;
    int grp = lane >> 2, qd = lane & 3;
    int mt = (wid >> 1) * 16;
    int NT = Nout >> 3;
    int ntBeg = (wid & 1) * (NT >> 1);
    int ntN   = NT >> 1;

    float acc[8][4];
    #pragma unroll
    for (int i = 0; i < 8; i++)
        #pragma unroll
        for (int j = 0; j < 4; j++) acc[i][j] = 0.f;

    gemm_mainloop(sAh, sAl, sBh, sBl, acc, mt, grp, qd, ntBeg, ntN);

    #pragma unroll
    for (int t = 0; t < 8; t++) {
        if (t >= ntN) break;
        int nt = ntBeg + t;
        int col = nt * 8 + 2 * qd;
        float bsum0 = bias ? bias[col]     : 0.f;
        float bsum1 = bias ? bias[col + 1] : 0.f;
        #pragma unroll
        for (int half = 0; half < 2; half++) {
            int row = m0 + mt + grp + half * 8;
            if (row >= M) continue;
            float v0 = acc[t][half * 2 + 0] + bsum0;
            float v1 = acc[t][half * 2 + 1] + bsum1;
            if (act) { v0 = gelu_f(v0); v1 = gelu_f(v1); }
            size_t base = (size_t)row * Nout + col;
            if (res) { v0 += res[base]; v1 += res[base + 1]; }
            *(float2*)(C + base) = make_float2(v0, v1);
            if (Chi) {
                __nv_bfloat16 h0 = __float2bfloat16(v0);
                __nv_bfloat16 h1 = __float2bfloat16(v1);
                __nv_bfloat162 hh; hh.x = h0; hh.y = h1;
                __nv_bfloat162 ll;
                ll.x = __float2bfloat16(v0 - __bfloat162float(h0));
                ll.y = __float2bfloat16(v1 - __bfloat162float(h1));
                *(__nv_bfloat162*)(Chi + base) = hh;
                *(__nv_bfloat162*)(Clo + base) = ll;
            }
        }
    }
}

// ---- fused Q/K/V/Skip GEMM: blockIdx.y selects weight set + output ----
struct QkvsPtrs {
    const __nv_bfloat16 *bh[4], *bl[4];
    float* c[4];
};

__global__ __launch_bounds__(512, 1) void qkvs_gemm(
    const __nv_bfloat16* __restrict__ Ahi, const __nv_bfloat16* __restrict__ Alo,
    QkvsPtrs pp, int M)
{
    extern __shared__ char smem[];
    __nv_bfloat16* sAh = (__nv_bfloat16*)(smem + OFF_AH);
    __nv_bfloat16* sAl = (__nv_bfloat16*)(smem + OFF_AL);
    __nv_bfloat16* sBh = (__nv_bfloat16*)(smem + OFF_BH);
    __nv_bfloat16* sBl = (__nv_bfloat16*)(smem + OFF_BL);
    int tid = threadIdx.x;
    int m0 = blockIdx.x * 128;
    int sel = blockIdx.y;

    gemm_stage_A(Ahi, Alo, sAh, sAl, m0, M, tid);
    gemm_stage_B(pp.bh[sel], pp.bl[sel], sBh, sBl, HID, tid);
    __syncthreads();

    int lane = tid & 31, wid = tid >> 5;
    int grp = lane >> 2, qd = lane & 3;
    int mt = (wid >> 1) * 16;
    int ntBeg = (wid & 1) * 8;

    float acc[8][4];
    #pragma unroll
    for (int i = 0; i < 8; i++)
        #pragma unroll
        for (int j = 0; j < 4; j++) acc[i][j] = 0.f;

    gemm_mainloop(sAh, sAl, sBh, sBl, acc, mt, grp, qd, ntBeg, 8);

    float* C = pp.c[sel];
    #pragma unroll
    for (int t = 0; t < 8; t++) {
        int nt = ntBeg + t;
        int col = nt * 8 + 2 * qd;
        #pragma unroll
        for (int half = 0; half < 2; half++) {
            int row = m0 + mt + grp + half * 8;
            if (row >= M) continue;
            size_t base = (size_t)row * HID + col;
            *(float2*)(C + base) = make_float2(acc[t][half * 2], acc[t][half * 2 + 1]);
        }
    }
}

// ======================= edge attention =====================================
__global__ __launch_bounds__(128) void attn_kernel(
    const float* __restrict__ q, const float* __restrict__ k,
    const float* __restrict__ v, const float* __restrict__ skip,
    const float* __restrict__ We, float* __restrict__ out,
    __nv_bfloat16* __restrict__ outhi, __nv_bfloat16* __restrict__ outlo)
{
    __shared__ float we_s[HID * 3];
    int tid = threadIdx.x;
    for (int i = tid; i < HID * 3; i += blockDim.x) we_s[i] = We[i];
    __syncthreads();

    int warp = blockIdx.x * (blockDim.x >> 5) + (tid >> 5);
    if (warp >= N_NODES) return;
    int lane = tid & 31;
    int col  = (lane >> 3) * DH + (lane & 7) * 4;

    float4 qv = *(const float4*)(q + (size_t)warp * HID + col);
    float m = -INFINITY, ssum = 0.f;
    float ox = 0.f, oy = 0.f, oz = 0.f, ow = 0.f;

    int e0 = g_off[warp], e1 = g_off[warp + 1];
    for (int e = e0; e < e1; e++) {
        int src = g_ssrc[e];
        float a0 = g_sattr[3 * e + 0];
        float a1 = g_sattr[3 * e + 1];
        float a2 = g_sattr[3 * e + 2];
        float4 kv = *(const float4*)(k + (size_t)src * HID + col);
        float4 vv = *(const float4*)(v + (size_t)src * HID + col);
        float ec0 = fmaf(a0, we_s[3*(col+0)+0], fmaf(a1, we_s[3*(col+0)+1], a2 * we_s[3*(col+0)+2]));
        float ec1 = fmaf(a0, we_s[3*(col+1)+0], fmaf(a1, we_s[3*(col+1)+1], a2 * we_s[3*(col+1)+2]));
        float ec2 = fmaf(a0, we_s[3*(col+2)+0], fmaf(a1, we_s[3*(col+2)+1], a2 * we_s[3*(col+2)+2]));
        float ec3 = fmaf(a0, we_s[3*(col+3)+0], fmaf(a1, we_s[3*(col+3)+1], a2 * we_s[3*(col+3)+2]));
        float kx = kv.x + ec0, ky = kv.y + ec1, kz = kv.z + ec2, kw = kv.w + ec3;
        float dot = qv.x * kx + qv.y * ky + qv.z * kz + qv.w * kw;
        dot += __shfl_xor_sync(0xffffffffu, dot, 1);
        dot += __shfl_xor_sync(0xffffffffu, dot, 2);
        dot += __shfl_xor_sync(0xffffffffu, dot, 4);
        float alpha = dot * 0.17677669529663687f;
        float nm = fmaxf(m, alpha);
        float sc = __expf(m - nm);
        float p  = __expf(alpha - nm);
        ssum = ssum * sc + p;
        ox = ox * sc + p * (vv.x + ec0);
        oy = oy * sc + p * (vv.y + ec1);
        oz = oz * sc + p * (vv.z + ec2);
        ow = ow * sc + p * (vv.w + ec3);
        m = nm;
    }
    float inv = 1.0f / fmaxf(ssum, 1e-16f);
    float4 sk = *(const float4*)(skip + (size_t)warp * HID + col);
    float o0 = ox * inv + sk.x, o1 = oy * inv + sk.y;
    float o2 = oz * inv + sk.z, o3 = ow * inv + sk.w;
    size_t base = (size_t)warp * HID + col;
    *(float4*)(out + base) = make_float4(o0, o1, o2, o3);

    float vs[4] = {o0, o1, o2, o3};
    #pragma unroll
    for (int pr = 0; pr < 2; pr++) {
        float v0 = vs[pr * 2], v1 = vs[pr * 2 + 1];
        __nv_bfloat16 h0 = __float2bfloat16(v0);
        __nv_bfloat16 h1 = __float2bfloat16(v1);
        __nv_bfloat162 hh; hh.x = h0; hh.y = h1;
        __nv_bfloat162 ll;
        ll.x = __float2bfloat16(v0 - __bfloat162float(h0));
        ll.y = __float2bfloat16(v1 - __bfloat162float(h1));
        *(__nv_bfloat162*)(outhi + base + pr * 2) = hh;
        *(__nv_bfloat162*)(outlo + base + pr * 2) = ll;
    }
}

// ======================= launch =============================================
static inline void run_mm(cudaStream_t s,
                          const __nv_bfloat16* Ahi, const __nv_bfloat16* Alo,
                          const __nv_bfloat16* Bhi, const __nv_bfloat16* Blo,
                          const float* bias, const float* res,
                          float* C, __nv_bfloat16* Chi, __nv_bfloat16* Clo,
                          int M, int Nout, int act) {
    int grid = (M + 127) / 128;
    mma_gemm<<<grid, 512, MMA_SMEM, s>>>(Ahi, Alo, Bhi, Blo, bias, res, C, Chi, Clo, M, Nout, act);
}

extern "C" void kernel_launch(void* const* d_in, const int* in_sizes, int n_in,
                              void* d_out, int out_size) {
    const float* x    = (const float*)d_in[0];
    const int*   ei   = (const int*)  d_in[1];
    const float* attr = (const float*)d_in[2];
    const float* Wq1 = (const float*)d_in[3],  *Wk1 = (const float*)d_in[4];
    const float* Wv1 = (const float*)d_in[5],  *We1 = (const float*)d_in[6];
    const float* Ws1 = (const float*)d_in[7];
    const float* M1a = (const float*)d_in[8],  *b1a = (const float*)d_in[9];
    const float* M1b = (const float*)d_in[10], *b1b = (const float*)d_in[11];
    const float* Wq2 = (const float*)d_in[12], *Wk2 = (const float*)d_in[13];
    const float* Wv2 = (const float*)d_in[14], *We2 = (const float*)d_in[15];
    const float* Ws2 = (const float*)d_in[16];
    const float* M2a = (const float*)d_in[17], *b2a = (const float*)d_in[18];
    const float* M2b = (const float*)d_in[19], *b2b = (const float*)d_in[20];
    const float* Wf1 = (const float*)d_in[21], *bf1 = (const float*)d_in[22];
    const float* Wf2 = (const float*)d_in[23], *bf2 = (const float*)d_in[24];
    float* out = (float*)d_out;

    float *q, *k, *v, *sk, *h, *t1, *t2;
    cudaGetSymbolAddress((void**)&q,  g_q);
    cudaGetSymbolAddress((void**)&k,  g_k);
    cudaGetSymbolAddress((void**)&v,  g_v);
    cudaGetSymbolAddress((void**)&sk, g_sk);
    cudaGetSymbolAddress((void**)&h,  g_h);
    cudaGetSymbolAddress((void**)&t1, g_t1);
    cudaGetSymbolAddress((void**)&t2, g_t2);

    __nv_bfloat16 *xhi, *xlo, *hhi, *hlo, *t1hi, *t1lo, *t2hi, *t2lo, *whi, *wlo;
    cudaGetSymbolAddress((void**)&xhi,  g_xhi);
    cudaGetSymbolAddress((void**)&xlo,  g_xlo);
    cudaGetSymbolAddress((void**)&hhi,  g_hhi);
    cudaGetSymbolAddress((void**)&hlo,  g_hlo);
    cudaGetSymbolAddress((void**)&t1hi, g_t1hi);
    cudaGetSymbolAddress((void**)&t1lo, g_t1lo);
    cudaGetSymbolAddress((void**)&t2hi, g_t2hi);
    cudaGetSymbolAddress((void**)&t2lo, g_t2lo);
    cudaGetSymbolAddress((void**)&whi,  g_whi);
    cudaGetSymbolAddress((void**)&wlo,  g_wlo);

    cudaFuncSetAttribute(mma_gemm,  cudaFuncAttributeMaxDynamicSharedMemorySize, MMA_SMEM);
    cudaFuncSetAttribute(qkvs_gemm, cudaFuncAttributeMaxDynamicSharedMemorySize, MMA_SMEM);

    cudaStream_t s = 0;
    #define WHI(i) (whi + (i) * 16384)
    #define WLO(i) (wlo + (i) * 16384)

    // 1: fused weight split + deg zero
    WPtrs wp;
    const float* wsrc[14] = {Wq1, Wk1, Wv1, Ws1, M1a, M1b, Wq2, Wk2, Wv2, Ws2, M2a, M2b, Wf1, Wf2};
    for (int i = 0; i < 14; i++) wp.p[i] = wsrc[i];
    wsplit_zero_kernel<<<WSPLIT_BLOCKS + ZERO_BLOCKS, 256, 0, s>>>(wp);
    // 2: x split
    split_kernel<<<(N_NODES * HID + 255) / 256, 256, 0, s>>>(x, xhi, xlo, N_NODES * HID);
    // 3-5: edge sort
    hist_kernel<<<(N_EDGES + 255) / 256, 256, 0, s>>>(ei);
    scan_kernel<<<1, 1024, 0, s>>>();
    scatter_kernel<<<(N_EDGES + 255) / 256, 256, 0, s>>>(ei, attr);

    int gblocks = (N_NODES + 127) / 128;
    int ablocks = (N_NODES * 32 + 127) / 128;

    // 6: layer-1 fused QKVS GEMM (ncu -s 5 -c 1 lands here)
    QkvsPtrs p1;
    for (int i = 0; i < 4; i++) { p1.bh[i] = WHI(i); p1.bl[i] = WLO(i); }
    p1.c[0] = q; p1.c[1] = k; p1.c[2] = v; p1.c[3] = sk;
    qkvs_gemm<<<dim3(gblocks, 4), 512, MMA_SMEM, s>>>(xhi, xlo, p1, N_NODES);

    attn_kernel<<<ablocks, 128, 0, s>>>(q, k, v, sk, We1, h, hhi, hlo);
    run_mm(s, hhi,  hlo,  WHI(4), WLO(4), b1a, nullptr, t1, t1hi, t1lo, N_NODES, HID, 1);
    run_mm(s, t1hi, t1lo, WHI(5), WLO(5), b1b, h,       t2, t2hi, t2lo, N_NODES, HID, 1);

    // layer-2 fused QKVS
    QkvsPtrs p2;
    for (int i = 0; i < 4; i++) { p2.bh[i] = WHI(6 + i); p2.bl[i] = WLO(6 + i); }
    p2.c[0] = q; p2.c[1] = k; p2.c[2] = v; p2.c[3] = sk;
    qkvs_gemm<<<dim3(gblocks, 4), 512, MMA_SMEM, s>>>(t2hi, t2lo, p2, N_NODES);

    attn_kernel<<<ablocks, 128, 0, s>>>(q, k, v, sk, We2, h, hhi, hlo);
    run_mm(s, hhi,  hlo,  WHI(10), WLO(10), b2a, nullptr, t1, t1hi, t1lo, N_NODES, HID, 1);
    run_mm(s, t1hi, t1lo, WHI(11), WLO(11), b2b, h,       t2, t2hi, t2lo, N_NODES, HID, 1);

    // final MLP
    run_mm(s, t2hi, t2lo, WHI(12), WLO(12), bf1, nullptr, t1, t1hi, t1lo, N_NODES, HID, 1);
    run_mm(s, t1hi, t1lo, WHI(13), WLO(13), bf2, nullptr, out, nullptr, nullptr, N_NODES, OUTD, 1);
}

// round 6
// speedup vs baseline: 1.2431x; 1.0009x over previous
#include <cuda_runtime.h>
#include <cuda_bf16.h>
#include <math.h>
#include <stdint.h>

#define N_NODES 50000
#define N_EDGES 800000
#define HID     128
#define NHEAD   4
#define DH      32
#define OUTD    64

// ======================= scratch (device globals) ===========================
__device__ float g_q [N_NODES * HID];
__device__ float g_k [N_NODES * HID];
__device__ float g_v [N_NODES * HID];
__device__ float g_sk[N_NODES * HID];
__device__ float g_h [N_NODES * HID];
__device__ float g_t1[N_NODES * HID];
__device__ float g_t2[N_NODES * HID];
__device__ int   g_deg [N_NODES];
__device__ int   g_off [N_NODES + 1];
__device__ int   g_cur [N_NODES];
__device__ int   g_ssrc[N_EDGES];
__device__ float g_sattr[N_EDGES * 3];

#define SCAN_NBLK 49
__device__ int g_bsum[SCAN_NBLK];
__device__ int g_bpre[SCAN_NBLK];

__device__ __nv_bfloat16 g_xhi [N_NODES * HID];
__device__ __nv_bfloat16 g_xlo [N_NODES * HID];
__device__ __nv_bfloat16 g_hhi [N_NODES * HID];
__device__ __nv_bfloat16 g_hlo [N_NODES * HID];
__device__ __nv_bfloat16 g_t1hi[N_NODES * HID];
__device__ __nv_bfloat16 g_t1lo[N_NODES * HID];
__device__ __nv_bfloat16 g_t2hi[N_NODES * HID];
__device__ __nv_bfloat16 g_t2lo[N_NODES * HID];
__device__ __nv_bfloat16 g_whi[14 * 16384];
__device__ __nv_bfloat16 g_wlo[14 * 16384];

// ============ fused: weight split + deg zero + x split (one launch) =========
struct WPtrs { const float* p[14]; };

#define WSPLIT_BLOCKS 864           // 13*64 + 32
#define ZERO_BLOCKS   196           // ceil(50000/256)
#define XSPLIT_BLOCKS 25000         // 50000*128/256

__global__ void bigsplit_kernel(WPtrs wp, const float* __restrict__ x) {
    int b = blockIdx.x;
    if (b < WSPLIT_BLOCKS) {
        int mi, cb;
        if (b < 832) { mi = b >> 6; cb = b & 63; }
        else         { mi = 13;     cb = b - 832; }
        int i = cb * 256 + threadIdx.x;
        int n = (mi == 13) ? 8192 : 16384;
        if (i < n) {
            float v = wp.p[mi][i];
            __nv_bfloat16 h = __float2bfloat16(v);
            g_whi[mi * 16384 + i] = h;
            g_wlo[mi * 16384 + i] = __float2bfloat16(v - __bfloat162float(h));
        }
    } else if (b < WSPLIT_BLOCKS + ZERO_BLOCKS) {
        int i = (b - WSPLIT_BLOCKS) * 256 + threadIdx.x;
        if (i < N_NODES) g_deg[i] = 0;
    } else {
        int i = (b - WSPLIT_BLOCKS - ZERO_BLOCKS) * 256 + threadIdx.x;
        float v = x[i];
        __nv_bfloat16 h = __float2bfloat16(v);
        g_xhi[i] = h;
        g_xlo[i] = __float2bfloat16(v - __bfloat162float(h));
    }
}

// ======================= edge sorting =======================================
__global__ void hist_kernel(const int* __restrict__ ei) {
    int e = blockIdx.x * blockDim.x + threadIdx.x;
    if (e < N_EDGES) atomicAdd(&g_deg[ei[N_EDGES + e]], 1);
}

// multi-block scan stage 1: per-block exclusive scan + block sum
__global__ __launch_bounds__(1024) void scan_s1() {
    __shared__ int wsum[32];
    int tid = threadIdx.x, lane = tid & 31, wid = tid >> 5;
    int i = blockIdx.x * 1024 + tid;
    int v = (i < N_NODES) ? g_deg[i] : 0;
    int x = v;
    #pragma unroll
    for (int d = 1; d < 32; d <<= 1) {
        int y = __shfl_up_sync(0xffffffffu, x, d);
        if (lane >= d) x += y;
    }
    if (lane == 31) wsum[wid] = x;
    __syncthreads();
    if (wid == 0) {
        int s = wsum[lane];
        #pragma unroll
        for (int d = 1; d < 32; d <<= 1) {
            int y = __shfl_up_sync(0xffffffffu, s, d);
            if (lane >= d) s += y;
        }
        wsum[lane] = s;
    }
    __syncthreads();
    int incl = x + (wid > 0 ? wsum[wid - 1] : 0);
    if (i < N_NODES) g_off[i] = incl - v;   // block-local exclusive
    if (tid == 1023) g_bsum[blockIdx.x] = incl;
}

// stage 2: serial scan over 49 block sums (trivial)
__global__ void scan_s2() {
    int run = 0;
    #pragma unroll 1
    for (int b = 0; b < SCAN_NBLK; b++) {
        g_bpre[b] = run;
        run += g_bsum[b];
    }
    g_off[N_NODES] = run;
}

// stage 3: add block prefix, fill g_cur
__global__ void scan_s3() {
    int i = blockIdx.x * blockDim.x + threadIdx.x;
    if (i < N_NODES) {
        int o = g_off[i] + g_bpre[i >> 10];
        g_off[i] = o;
        g_cur[i] = o;
    }
}

__global__ void scatter_kernel(const int* __restrict__ ei, const float* __restrict__ attr) {
    int e = blockIdx.x * blockDim.x + threadIdx.x;
    if (e < N_EDGES) {
        int dst = ei[N_EDGES + e];
        int pos = atomicAdd(&g_cur[dst], 1);
        g_ssrc[pos] = ei[e];
        g_sattr[3 * pos + 0] = attr[3 * e + 0];
        g_sattr[3 * pos + 1] = attr[3 * e + 1];
        g_sattr[3 * pos + 2] = attr[3 * e + 2];
    }
}

// ======================= GELU ==============================================
__device__ __forceinline__ float gelu_f(float x) {
    float x3 = x * x * x;
    float u = 0.7978845608028654f * (x + 0.044715f * x3);
    return 0.5f * x * (1.0f + tanhf(u));
}

// ======================= HMMA mma.sync GEMM =================================
#define SROW 136
#define OFF_AH 0
#define OFF_AL 34816
#define OFF_BH 69632
#define OFF_BL 104448
#define MMA_SMEM 139264

__device__ __forceinline__ uint32_t lds32(const __nv_bfloat16* p) {
    return *(const uint32_t*)p;
}

__device__ __forceinline__ void mma16816(float* c,
    uint32_t a0, uint32_t a1, uint32_t a2, uint32_t a3,
    uint32_t b0, uint32_t b1) {
    asm volatile(
        "mma.sync.aligned.m16n8k16.row.col.f32.bf16.bf16.f32 "
        "{%0,%1,%2,%3}, {%4,%5,%6,%7}, {%8,%9}, {%0,%1,%2,%3};"
        : "+f"(c[0]), "+f"(c[1]), "+f"(c[2]), "+f"(c[3])
        : "r"(a0), "r"(a1), "r"(a2), "r"(a3), "r"(b0), "r"(b1));
}

__device__ __forceinline__ void gemm_stage_A(
    const __nv_bfloat16* Ahi, const __nv_bfloat16* Alo,
    __nv_bfloat16* sAh, __nv_bfloat16* sAl, int m0, int M, int tid)
{
    int row = tid >> 2;
    int u0  = (tid & 3) * 4;
    int gr  = m0 + row;
    bool ok = gr < M;
    const uint4* ah = (const uint4*)(Ahi + (size_t)gr * 128);
    const uint4* al = (const uint4*)(Alo + (size_t)gr * 128);
    uint4 z = make_uint4(0u, 0u, 0u, 0u);
    #pragma unroll
    for (int u = u0; u < u0 + 4; u++) {
        *(uint4*)(&sAh[row * SROW + u * 8]) = ok ? ah[u] : z;
        *(uint4*)(&sAl[row * SROW + u * 8]) = ok ? al[u] : z;
    }
}

__device__ __forceinline__ void gemm_stage_B(
    const __nv_bfloat16* Bhi, const __nv_bfloat16* Blo,
    __nv_bfloat16* sBh, __nv_bfloat16* sBl, int Nout, int tid)
{
    if (tid < Nout * 4) {
        int row = tid >> 2;
        int u0  = (tid & 3) * 4;
        const uint4* bh = (const uint4*)(Bhi + (size_t)row * 128);
        const uint4* bl = (const uint4*)(Blo + (size_t)row * 128);
        #pragma unroll
        for (int u = u0; u < u0 + 4; u++) {
            *(uint4*)(&sBh[row * SROW + u * 8]) = bh[u];
            *(uint4*)(&sBl[row * SROW + u * 8]) = bl[u];
        }
    }
}

__device__ __forceinline__ void gemm_mainloop(
    const __nv_bfloat16* sAh, const __nv_bfloat16* sAl,
    const __nv_bfloat16* sBh, const __nv_bfloat16* sBl,
    float acc[8][4], int mt, int grp, int qd, int ntBeg, int ntN)
{
    for (int kt = 0; kt < 128; kt += 16) {
        int aoff = (mt + grp) * SROW + kt + 2 * qd;
        uint32_t ah0 = lds32(sAh + aoff);
        uint32_t ah1 = lds32(sAh + aoff + 8 * SROW);
        uint32_t ah2 = lds32(sAh + aoff + 8);
        uint32_t ah3 = lds32(sAh + aoff + 8 * SROW + 8);
        uint32_t al0 = lds32(sAl + aoff);
        uint32_t al1 = lds32(sAl + aoff + 8 * SROW);
        uint32_t al2 = lds32(sAl + aoff + 8);
        uint32_t al3 = lds32(sAl + aoff + 8 * SROW + 8);
        #pragma unroll
        for (int t = 0; t < 8; t++) {
            if (t >= ntN) break;
            int nt = ntBeg + t;
            int boff = (nt * 8 + grp) * SROW + kt + 2 * qd;
            uint32_t bh0 = lds32(sBh + boff);
            uint32_t bh1 = lds32(sBh + boff + 8);
            uint32_t bl0 = lds32(sBl + boff);
            uint32_t bl1 = lds32(sBl + boff + 8);
            mma16816(acc[t], ah0, ah1, ah2, ah3, bh0, bh1);
            mma16816(acc[t], ah0, ah1, ah2, ah3, bl0, bl1);
            mma16816(acc[t], al0, al1, al2, al3, bh0, bh1);
        }
    }
}

__global__ __launch_bounds__(512, 1) void mma_gemm(
    const __nv_bfloat16* __restrict__ Ahi, const __nv_bfloat16* __restrict__ Alo,
    const __nv_bfloat16* __restrict__ Bhi, const __nv_bfloat16* __restrict__ Blo,
    const float* __restrict__ bias, const float* __restrict__ res,
    float* __restrict__ C, __nv_bfloat16* __restrict__ Chi, __nv_bfloat16* __restrict__ Clo,
    int M, int Nout, int act)
{
    extern __shared__ char smem[];
    __nv_bfloat16* sAh = (__nv_bfloat16*)(smem + OFF_AH);
    __nv_bfloat16* sAl = (__nv_bfloat16*)(smem + OFF_AL);
    __nv_bfloat16* sBh = (__nv_bfloat16*)(smem + OFF_BH);
    __nv_bfloat16* sBl = (__nv_bfloat16*)(smem + OFF_BL);
    int tid = threadIdx.x;
    int m0 = blockIdx.x * 128;

    gemm_stage_A(Ahi, Alo, sAh, sAl, m0, M, tid);
    gemm_stage_B(Bhi, Blo, sBh, sBl, Nout, tid);
    __syncthreads();

    int lane = tid & 31, wid = tid >> 5;
    int grp = lane >> 2, qd = lane & 3;
    int mt = (wid >> 1) * 16;
    int NT = Nout >> 3;
    int ntBeg = (wid & 1) * (NT >> 1);
    int ntN   = NT >> 1;

    float acc[8][4];
    #pragma unroll
    for (int i = 0; i < 8; i++)
        #pragma unroll
        for (int j = 0; j < 4; j++) acc[i][j] = 0.f;

    gemm_mainloop(sAh, sAl, sBh, sBl, acc, mt, grp, qd, ntBeg, ntN);

    #pragma unroll
    for (int t = 0; t < 8; t++) {
        if (t >= ntN) break;
        int nt = ntBeg + t;
        int col = nt * 8 + 2 * qd;
        float bsum0 = bias ? bias[col]     : 0.f;
        float bsum1 = bias ? bias[col + 1] : 0.f;
        #pragma unroll
        for (int half = 0; half < 2; half++) {
            int row = m0 + mt + grp + half * 8;
            if (row >= M) continue;
            float v0 = acc[t][half * 2 + 0] + bsum0;
            float v1 = acc[t][half * 2 + 1] + bsum1;
            if (act) { v0 = gelu_f(v0); v1 = gelu_f(v1); }
            size_t base = (size_t)row * Nout + col;
            if (res) { v0 += res[base]; v1 += res[base + 1]; }
            *(float2*)(C + base) = make_float2(v0, v1);
            if (Chi) {
                __nv_bfloat16 h0 = __float2bfloat16(v0);
                __nv_bfloat16 h1 = __float2bfloat16(v1);
                __nv_bfloat162 hh; hh.x = h0; hh.y = h1;
                __nv_bfloat162 ll;
                ll.x = __float2bfloat16(v0 - __bfloat162float(h0));
                ll.y = __float2bfloat16(v1 - __bfloat162float(h1));
                *(__nv_bfloat162*)(Chi + base) = hh;
                *(__nv_bfloat162*)(Clo + base) = ll;
            }
        }
    }
}

struct QkvsPtrs {
    const __nv_bfloat16 *bh[4], *bl[4];
    float* c[4];
};

__global__ __launch_bounds__(512, 1) void qkvs_gemm(
    const __nv_bfloat16* __restrict__ Ahi, const __nv_bfloat16* __restrict__ Alo,
    QkvsPtrs pp, int M)
{
    extern __shared__ char smem[];
    __nv_bfloat16* sAh = (__nv_bfloat16*)(smem + OFF_AH);
    __nv_bfloat16* sAl = (__nv_bfloat16*)(smem + OFF_AL);
    __nv_bfloat16* sBh = (__nv_bfloat16*)(smem + OFF_BH);
    __nv_bfloat16* sBl = (__nv_bfloat16*)(smem + OFF_BL);
    int tid = threadIdx.x;
    int m0 = blockIdx.x * 128;
    int sel = blockIdx.y;

    gemm_stage_A(Ahi, Alo, sAh, sAl, m0, M, tid);
    gemm_stage_B(pp.bh[sel], pp.bl[sel], sBh, sBl, HID, tid);
    __syncthreads();

    int lane = tid & 31, wid = tid >> 5;
    int grp = lane >> 2, qd = lane & 3;
    int mt = (wid >> 1) * 16;
    int ntBeg = (wid & 1) * 8;

    float acc[8][4];
    #pragma unroll
    for (int i = 0; i < 8; i++)
        #pragma unroll
        for (int j = 0; j < 4; j++) acc[i][j] = 0.f;

    gemm_mainloop(sAh, sAl, sBh, sBl, acc, mt, grp, qd, ntBeg, 8);

    float* C = pp.c[sel];
    #pragma unroll
    for (int t = 0; t < 8; t++) {
        int nt = ntBeg + t;
        int col = nt * 8 + 2 * qd;
        #pragma unroll
        for (int half = 0; half < 2; half++) {
            int row = m0 + mt + grp + half * 8;
            if (row >= M) continue;
            size_t base = (size_t)row * HID + col;
            *(float2*)(C + base) = make_float2(acc[t][half * 2], acc[t][half * 2 + 1]);
        }
    }
}

// ======================= edge attention (unroll-4, reg-resident We) =========
__global__ __launch_bounds__(128) void attn_kernel(
    const float* __restrict__ q, const float* __restrict__ k,
    const float* __restrict__ v, const float* __restrict__ skip,
    const float* __restrict__ We, float* __restrict__ out,
    __nv_bfloat16* __restrict__ outhi, __nv_bfloat16* __restrict__ outlo)
{
    __shared__ float we_s[HID * 3];
    int tid = threadIdx.x;
    for (int i = tid; i < HID * 3; i += blockDim.x) we_s[i] = We[i];
    __syncthreads();

    int warp = blockIdx.x * (blockDim.x >> 5) + (tid >> 5);
    if (warp >= N_NODES) return;
    int lane = tid & 31;
    int col  = (lane >> 3) * DH + (lane & 7) * 4;

    // hoist per-lane We rows into registers (loop-invariant)
    float wr[12];
    #pragma unroll
    for (int i = 0; i < 4; i++)
        #pragma unroll
        for (int c = 0; c < 3; c++)
            wr[i * 3 + c] = we_s[3 * (col + i) + c];

    float4 qv = *(const float4*)(q + (size_t)warp * HID + col);
    float m = -INFINITY, ssum = 0.f;
    float ox = 0.f, oy = 0.f, oz = 0.f, ow = 0.f;

    int e0 = g_off[warp], e1 = g_off[warp + 1];
    int e = e0;
    int ebulk = e0 + ((e1 - e0) & ~3);

    for (; e < ebulk; e += 4) {
        int srcs[4];
        float a0s[4], a1s[4], a2s[4];
        float4 kvs[4], vvs[4];
        #pragma unroll
        for (int j = 0; j < 4; j++) srcs[j] = g_ssrc[e + j];
        #pragma unroll
        for (int j = 0; j < 4; j++) {
            a0s[j] = g_sattr[3 * (e + j) + 0];
            a1s[j] = g_sattr[3 * (e + j) + 1];
            a2s[j] = g_sattr[3 * (e + j) + 2];
        }
        #pragma unroll
        for (int j = 0; j < 4; j++) {
            kvs[j] = *(const float4*)(k + (size_t)srcs[j] * HID + col);
            vvs[j] = *(const float4*)(v + (size_t)srcs[j] * HID + col);
        }
        #pragma unroll
        for (int j = 0; j < 4; j++) {
            float ec0 = fmaf(a0s[j], wr[0], fmaf(a1s[j], wr[1],  a2s[j] * wr[2]));
            float ec1 = fmaf(a0s[j], wr[3], fmaf(a1s[j], wr[4],  a2s[j] * wr[5]));
            float ec2 = fmaf(a0s[j], wr[6], fmaf(a1s[j], wr[7],  a2s[j] * wr[8]));
            float ec3 = fmaf(a0s[j], wr[9], fmaf(a1s[j], wr[10], a2s[j] * wr[11]));
            float kx = kvs[j].x + ec0, ky = kvs[j].y + ec1;
            float kz = kvs[j].z + ec2, kw = kvs[j].w + ec3;
            float dot = qv.x * kx + qv.y * ky + qv.z * kz + qv.w * kw;
            dot += __shfl_xor_sync(0xffffffffu, dot, 1);
            dot += __shfl_xor_sync(0xffffffffu, dot, 2);
            dot += __shfl_xor_sync(0xffffffffu, dot, 4);
            float alpha = dot * 0.17677669529663687f;
            float nm = fmaxf(m, alpha);
            float sc = __expf(m - nm);
            float p  = __expf(alpha - nm);
            ssum = ssum * sc + p;
            ox = ox * sc + p * (vvs[j].x + ec0);
            oy = oy * sc + p * (vvs[j].y + ec1);
            oz = oz * sc + p * (vvs[j].z + ec2);
            ow = ow * sc + p * (vvs[j].w + ec3);
            m = nm;
        }
    }
    for (; e < e1; e++) {
        int src = g_ssrc[e];
        float a0 = g_sattr[3 * e + 0];
        float a1 = g_sattr[3 * e + 1];
        float a2 = g_sattr[3 * e + 2];
        float4 kv = *(const float4*)(k + (size_t)src * HID + col);
        float4 vv = *(const float4*)(v + (size_t)src * HID + col);
        float ec0 = fmaf(a0, wr[0], fmaf(a1, wr[1],  a2 * wr[2]));
        float ec1 = fmaf(a0, wr[3], fmaf(a1, wr[4],  a2 * wr[5]));
        float ec2 = fmaf(a0, wr[6], fmaf(a1, wr[7],  a2 * wr[8]));
        float ec3 = fmaf(a0, wr[9], fmaf(a1, wr[10], a2 * wr[11]));
        float kx = kv.x + ec0, ky = kv.y + ec1, kz = kv.z + ec2, kw = kv.w + ec3;
        float dot = qv.x * kx + qv.y * ky + qv.z * kz + qv.w * kw;
        dot += __shfl_xor_sync(0xffffffffu, dot, 1);
        dot += __shfl_xor_sync(0xffffffffu, dot, 2);
        dot += __shfl_xor_sync(0xffffffffu, dot, 4);
        float alpha = dot * 0.17677669529663687f;
        float nm = fmaxf(m, alpha);
        float sc = __expf(m - nm);
        float p  = __expf(alpha - nm);
        ssum = ssum * sc + p;
        ox = ox * sc + p * (vv.x + ec0);
        oy = oy * sc + p * (vv.y + ec1);
        oz = oz * sc + p * (vv.z + ec2);
        ow = ow * sc + p * (vv.w + ec3);
        m = nm;
    }

    float inv = 1.0f / fmaxf(ssum, 1e-16f);
    float4 sk = *(const float4*)(skip + (size_t)warp * HID + col);
    float o0 = ox * inv + sk.x, o1 = oy * inv + sk.y;
    float o2 = oz * inv + sk.z, o3 = ow * inv + sk.w;
    size_t base = (size_t)warp * HID + col;
    *(float4*)(out + base) = make_float4(o0, o1, o2, o3);

    float vs[4] = {o0, o1, o2, o3};
    #pragma unroll
    for (int pr = 0; pr < 2; pr++) {
        float v0 = vs[pr * 2], v1 = vs[pr * 2 + 1];
        __nv_bfloat16 h0 = __float2bfloat16(v0);
        __nv_bfloat16 h1 = __float2bfloat16(v1);
        __nv_bfloat162 hh; hh.x = h0; hh.y = h1;
        __nv_bfloat162 ll;
        ll.x = __float2bfloat16(v0 - __bfloat162float(h0));
        ll.y = __float2bfloat16(v1 - __bfloat162float(h1));
        *(__nv_bfloat162*)(outhi + base + pr * 2) = hh;
        *(__nv_bfloat162*)(outlo + base + pr * 2) = ll;
    }
}

// ======================= launch =============================================
static inline void run_mm(cudaStream_t s,
                          const __nv_bfloat16* Ahi, const __nv_bfloat16* Alo,
                          const __nv_bfloat16* Bhi, const __nv_bfloat16* Blo,
                          const float* bias, const float* res,
                          float* C, __nv_bfloat16* Chi, __nv_bfloat16* Clo,
                          int M, int Nout, int act) {
    int grid = (M + 127) / 128;
    mma_gemm<<<grid, 512, MMA_SMEM, s>>>(Ahi, Alo, Bhi, Blo, bias, res, C, Chi, Clo, M, Nout, act);
}

extern "C" void kernel_launch(void* const* d_in, const int* in_sizes, int n_in,
                              void* d_out, int out_size) {
    const float* x    = (const float*)d_in[0];
    const int*   ei   = (const int*)  d_in[1];
    const float* attr = (const float*)d_in[2];
    const float* Wq1 = (const float*)d_in[3],  *Wk1 = (const float*)d_in[4];
    const float* Wv1 = (const float*)d_in[5],  *We1 = (const float*)d_in[6];
    const float* Ws1 = (const float*)d_in[7];
    const float* M1a = (const float*)d_in[8],  *b1a = (const float*)d_in[9];
    const float* M1b = (const float*)d_in[10], *b1b = (const float*)d_in[11];
    const float* Wq2 = (const float*)d_in[12], *Wk2 = (const float*)d_in[13];
    const float* Wv2 = (const float*)d_in[14], *We2 = (const float*)d_in[15];
    const float* Ws2 = (const float*)d_in[16];
    const float* M2a = (const float*)d_in[17], *b2a = (const float*)d_in[18];
    const float* M2b = (const float*)d_in[19], *b2b = (const float*)d_in[20];
    const float* Wf1 = (const float*)d_in[21], *bf1 = (const float*)d_in[22];
    const float* Wf2 = (const float*)d_in[23], *bf2 = (const float*)d_in[24];
    float* out = (float*)d_out;

    float *q, *k, *v, *sk, *h, *t1, *t2;
    cudaGetSymbolAddress((void**)&q,  g_q);
    cudaGetSymbolAddress((void**)&k,  g_k);
    cudaGetSymbolAddress((void**)&v,  g_v);
    cudaGetSymbolAddress((void**)&sk, g_sk);
    cudaGetSymbolAddress((void**)&h,  g_h);
    cudaGetSymbolAddress((void**)&t1, g_t1);
    cudaGetSymbolAddress((void**)&t2, g_t2);

    __nv_bfloat16 *xhi, *xlo, *hhi, *hlo, *t1hi, *t1lo, *t2hi, *t2lo, *whi, *wlo;
    cudaGetSymbolAddress((void**)&xhi,  g_xhi);
    cudaGetSymbolAddress((void**)&xlo,  g_xlo);
    cudaGetSymbolAddress((void**)&hhi,  g_hhi);
    cudaGetSymbolAddress((void**)&hlo,  g_hlo);
    cudaGetSymbolAddress((void**)&t1hi, g_t1hi);
    cudaGetSymbolAddress((void**)&t1lo, g_t1lo);
    cudaGetSymbolAddress((void**)&t2hi, g_t2hi);
    cudaGetSymbolAddress((void**)&t2lo, g_t2lo);
    cudaGetSymbolAddress((void**)&whi,  g_whi);
    cudaGetSymbolAddress((void**)&wlo,  g_wlo);

    cudaFuncSetAttribute(mma_gemm,  cudaFuncAttributeMaxDynamicSharedMemorySize, MMA_SMEM);
    cudaFuncSetAttribute(qkvs_gemm, cudaFuncAttributeMaxDynamicSharedMemorySize, MMA_SMEM);

    cudaStream_t s = 0;
    #define WHI(i) (whi + (i) * 16384)
    #define WLO(i) (wlo + (i) * 16384)

    int gblocks = (N_NODES + 127) / 128;
    int ablocks = (N_NODES * 32 + 127) / 128;

    // 1: all splits + deg zero
    WPtrs wp;
    const float* wsrc[14] = {Wq1, Wk1, Wv1, Ws1, M1a, M1b, Wq2, Wk2, Wv2, Ws2, M2a, M2b, Wf1, Wf2};
    for (int i = 0; i < 14; i++) wp.p[i] = wsrc[i];
    bigsplit_kernel<<<WSPLIT_BLOCKS + ZERO_BLOCKS + XSPLIT_BLOCKS, 256, 0, s>>>(wp, x);
    // 2: hist
    hist_kernel<<<(N_EDGES + 255) / 256, 256, 0, s>>>(ei);
    // 3: scan stage 1
    scan_s1<<<SCAN_NBLK, 1024, 0, s>>>();
    // 4: layer-1 fused QKVS GEMM  (ncu capture lands here)
    QkvsPtrs p1;
    for (int i = 0; i < 4; i++) { p1.bh[i] = WHI(i); p1.bl[i] = WLO(i); }
    p1.c[0] = q; p1.c[1] = k; p1.c[2] = v; p1.c[3] = sk;
    qkvs_gemm<<<dim3(gblocks, 4), 512, MMA_SMEM, s>>>(xhi, xlo, p1, N_NODES);
    // 5-6: scan stages 2,3
    scan_s2<<<1, 1, 0, s>>>();
    scan_s3<<<(N_NODES + 255) / 256, 256, 0, s>>>();
    // 7: scatter
    scatter_kernel<<<(N_EDGES + 255) / 256, 256, 0, s>>>(ei, attr);

    // layer 1
    attn_kernel<<<ablocks, 128, 0, s>>>(q, k, v, sk, We1, h, hhi, hlo);
    run_mm(s, hhi,  hlo,  WHI(4), WLO(4), b1a, nullptr, t1, t1hi, t1lo, N_NODES, HID, 1);
    run_mm(s, t1hi, t1lo, WHI(5), WLO(5), b1b, h,       t2, t2hi, t2lo, N_NODES, HID, 1);

    // layer 2
    QkvsPtrs p2;
    for (int i = 0; i < 4; i++) { p2.bh[i] = WHI(6 + i); p2.bl[i] = WLO(6 + i); }
    p2.c[0] = q; p2.c[1] = k; p2.c[2] = v; p2.c[3] = sk;
    qkvs_gemm<<<dim3(gblocks, 4), 512, MMA_SMEM, s>>>(t2hi, t2lo, p2, N_NODES);
    attn_kernel<<<ablocks, 128, 0, s>>>(q, k, v, sk, We2, h, hhi, hlo);
    run_mm(s, hhi,  hlo,  WHI(10), WLO(10), b2a, nullptr, t1, t1hi, t1lo, N_NODES, HID, 1);
    run_mm(s, t1hi, t1lo, WHI(11), WLO(11), b2b, h,       t2, t2hi, t2lo, N_NODES, HID, 1);

    // final MLP
    run_mm(s, t2hi, t2lo, WHI(12), WLO(12), bf1, nullptr, t1, t1hi, t1lo, N_NODES, HID, 1);
    run_mm(s, t1hi, t1lo, WHI(13), WLO(13), bf2, nullptr, out, nullptr, nullptr, N_NODES, OUTD, 1);
}